// round 5
// baseline (speedup 1.0000x reference)
#include <cuda_runtime.h>
#include <cstdint>

#define LL    256   // sequence length
#define EE    64    // embed dim
#define HH    64    // hidden
#define GG    256   // 4H
#define NSEQ  2048  // B*S
#define NTHR  512

typedef unsigned long long u64;

// 1 GB scratch: pre[dir][n][t][j*4+g]  (input projection + bias, both directions)
__device__ float g_pre[(size_t)2 * NSEQ * LL * GG];

__device__ __forceinline__ void fma2(u64 &d, u64 a, u64 b) {
    asm("fma.rn.f32x2 %0, %1, %2, %0;" : "+l"(d) : "l"(a), "l"(b));
}
__device__ __forceinline__ u64 pack2(float lo, float hi) {
    u64 r; asm("mov.b64 %0, {%1, %2};" : "=l"(r) : "f"(lo), "f"(hi)); return r;
}
__device__ __forceinline__ float hsum2(u64 v) {
    float lo, hi; asm("mov.b64 {%0, %1}, %2;" : "=f"(lo), "=f"(hi) : "l"(v));
    return lo + hi;
}
__device__ __forceinline__ float fsig(float x) {
    return __fdividef(1.f, 1.f + __expf(-x));
}
__device__ __forceinline__ float ftanh(float x) {
    return 2.f * __fdividef(1.f, 1.f + __expf(-2.f * x)) - 1.f;
}

#define XSTRIDE 68

// ============================================================================
// Kernel 1: pre[dir][m][g] = embed[ids[m]] @ Wk_dir + b_dir   (m = n*LL + t)
// 512 threads, 64-row subtiles (8/thread), double-buffered xs, 1 bar/subtile.
// Weight layout in SMEM (K-paired for f32x2):
//   wk0[e2*256 + j*4 + g*2 + s] = Wk[(2*e2+s)*GG + g*64 + j]      g in {i,f}
//   wk1[e2*256 + j*4 + g*2 + s] = Wk[(2*e2+s)*GG + (g+2)*64 + j]  g in {g,o}
// ============================================================================
#define K1_ROWS 64
#define K1_SUBS 4
#define K1_SMEM_FLOATS (16384 + 2 * (K1_ROWS * XSTRIDE))

__global__ void __launch_bounds__(NTHR, 1)
pre_kernel(const int* __restrict__ ids,
           const float* __restrict__ embed,
           const float* __restrict__ Wk_f, const float* __restrict__ b_f,
           const float* __restrict__ Wk_b, const float* __restrict__ b_b)
{
    extern __shared__ float smem[];
    float* wk0   = smem;
    float* wk1   = smem + 8192;
    float* xsbuf = smem + 16384;        // 2 x [64][68]

    const int tid = threadIdx.x;
    const int dir = blockIdx.y;
    const float* Wk = dir ? Wk_b : Wk_f;
    const float* bb = dir ? b_b  : b_f;

    for (int idx = tid; idx < 8192; idx += NTHR) {
        int e2  = idx >> 8;
        int rem = idx & 255;
        int jj  = rem >> 2;
        int g   = (rem >> 1) & 1;
        int s   = rem & 1;
        int e   = 2 * e2 + s;
        wk0[idx] = Wk[e * GG + g * 64 + jj];
        wk1[idx] = Wk[e * GG + (g + 2) * 64 + jj];
    }

    const int j  = tid & 63;
    const int q  = tid >> 6;            // 0..7
    const int r0 = q * 8;
    const float bi = bb[j], bf = bb[64 + j], bg = bb[128 + j], bo = bb[192 + j];

    const int gr = tid >> 3;            // row 0..63
    const int ge = (tid & 7) * 8;       // e offset

    const size_t m_base = (size_t)blockIdx.x * (K1_ROWS * K1_SUBS);
    const size_t dbase  = (size_t)dir * NSEQ * LL;

    // gather subtile 0 into buffer 0
    {
        int id = ids[m_base + gr];
        const float4* src = (const float4*)(embed + (size_t)id * EE + ge);
        float4 v0 = src[0];
        float4 v1 = src[1];
        float4* dst = (float4*)&xsbuf[gr * XSTRIDE + ge];
        dst[0] = v0;
        dst[1] = v1;
    }

    int buf = 0;
    for (int sub = 0; sub < K1_SUBS; ++sub) {
        __syncthreads();   // xs[buf] ready (and weights on sub=0); xs[buf^1] free
        float* xs = xsbuf + buf * (K1_ROWS * XSTRIDE);

        // prefetch next subtile's embed rows into registers (lands under compute)
        float4 n0, n1;
        if (sub + 1 < K1_SUBS) {
            int id = ids[m_base + (size_t)(sub + 1) * K1_ROWS + gr];
            const float4* src = (const float4*)(embed + (size_t)id * EE + ge);
            n0 = src[0];
            n1 = src[1];
        }

        u64 a0[8], a1[8], a2[8], a3[8];
#pragma unroll
        for (int p = 0; p < 8; ++p) {
            a0[p] = pack2(bi, 0.f);
            a1[p] = pack2(bf, 0.f);
            a2[p] = pack2(bg, 0.f);
            a3[p] = pack2(bo, 0.f);
        }

#pragma unroll 2
        for (int e4 = 0; e4 < 16; ++e4) {
            const ulonglong2 wA0 = *(const ulonglong2*)(wk0 + (2 * e4) * 256 + j * 4);
            const ulonglong2 wB0 = *(const ulonglong2*)(wk1 + (2 * e4) * 256 + j * 4);
            const ulonglong2 wA1 = *(const ulonglong2*)(wk0 + (2 * e4 + 1) * 256 + j * 4);
            const ulonglong2 wB1 = *(const ulonglong2*)(wk1 + (2 * e4 + 1) * 256 + j * 4);
#pragma unroll
            for (int p = 0; p < 8; ++p) {
                ulonglong2 x4 = *(const ulonglong2*)(xs + (r0 + p) * XSTRIDE + e4 * 4);
                fma2(a0[p], x4.x, wA0.x);
                fma2(a1[p], x4.x, wA0.y);
                fma2(a2[p], x4.x, wB0.x);
                fma2(a3[p], x4.x, wB0.y);
                fma2(a0[p], x4.y, wA1.x);
                fma2(a1[p], x4.y, wA1.y);
                fma2(a2[p], x4.y, wB1.x);
                fma2(a3[p], x4.y, wB1.y);
            }
        }

        const size_t m0 = m_base + (size_t)sub * K1_ROWS;
#pragma unroll
        for (int p = 0; p < 8; ++p) {
            float4 r;
            r.x = hsum2(a0[p]);
            r.y = hsum2(a1[p]);
            r.z = hsum2(a2[p]);
            r.w = hsum2(a3[p]);
            *(float4*)&g_pre[(dbase + m0 + r0 + p) * GG + j * 4] = r;
        }

        // stage next subtile into the other buffer
        if (sub + 1 < K1_SUBS) {
            float* xn = xsbuf + (buf ^ 1) * (K1_ROWS * XSTRIDE);
            float4* dst = (float4*)&xn[gr * XSTRIDE + ge];
            dst[0] = n0;
            dst[1] = n1;
        }
        buf ^= 1;
    }
}

// ============================================================================
// Kernel 2: recurrence only (h @ Wr per step). 512 threads, 4 rows/thread,
// double-buffered hs (1 barrier/step), pre prefetched 1 step ahead in regs.
// ============================================================================
#define ROWS 32
#define K2_SMEM_FLOATS (16384 + 2 * (ROWS * XSTRIDE))

__global__ void __launch_bounds__(NTHR, 1)
rec_kernel(const float* __restrict__ Wr_f,
           const float* __restrict__ Wr_b,
           float* __restrict__ out)
{
    extern __shared__ float smem[];
    float* wr0   = smem;
    float* wr1   = smem + 8192;
    float* hsbuf = smem + 16384;       // 2 x [32][68]

    const int tid   = threadIdx.x;
    const int dir   = blockIdx.y;
    const int nbase = blockIdx.x * ROWS;
    const float* Wr = dir ? Wr_b : Wr_f;

    for (int idx = tid; idx < 8192; idx += NTHR) {
        int e2  = idx >> 8;
        int rem = idx & 255;
        int jj  = rem >> 2;
        int g   = (rem >> 1) & 1;
        int s   = rem & 1;
        int e   = 2 * e2 + s;
        wr0[idx] = Wr[e * GG + g * 64 + jj];
        wr1[idx] = Wr[e * GG + (g + 2) * 64 + jj];
    }

    const int j  = tid & 63;
    const int q  = tid >> 6;           // 0..7
    const int r0 = q * 4;              // 4 rows per thread

    const float* preb = g_pre + (size_t)dir * NSEQ * LL * GG;

    float c_[4], h_[4];
    float4 pv[4];
#pragma unroll
    for (int p = 0; p < 4; ++p) { c_[p] = 0.f; h_[p] = 0.f; }

    // prefetch pre for step 0
    {
        const int te0 = dir ? (LL - 1) : 0;
#pragma unroll
        for (int p = 0; p < 4; ++p)
            pv[p] = *(const float4*)&preb[((size_t)(nbase + r0 + p) * LL + te0) * GG + j * 4];
    }

    __syncthreads();   // weights ready

    int buf = 0;
    for (int t = 0; t < LL; ++t) {
        const int te = dir ? (LL - 1 - t) : t;
        float* hs = hsbuf + buf * (ROWS * XSTRIDE);

        // publish h_t
#pragma unroll
        for (int p = 0; p < 4; ++p)
            hs[(r0 + p) * XSTRIDE + j] = h_[p];
        __syncthreads();

        // consume prefetched pre into accumulators
        u64 a0[4], a1[4], a2[4], a3[4];
#pragma unroll
        for (int p = 0; p < 4; ++p) {
            a0[p] = pack2(pv[p].x, 0.f);
            a1[p] = pack2(pv[p].y, 0.f);
            a2[p] = pack2(pv[p].z, 0.f);
            a3[p] = pack2(pv[p].w, 0.f);
        }

        // issue prefetch for step t+1 (lands during the compute below)
        {
            const int tn = (t + 1 < LL) ? (dir ? (LL - 2 - t) : (t + 1)) : te;
#pragma unroll
            for (int p = 0; p < 4; ++p)
                pv[p] = *(const float4*)&preb[((size_t)(nbase + r0 + p) * LL + tn) * GG + j * 4];
        }

        if (t != 0) {   // h == 0 at t==0: skip the matmul
#pragma unroll 4
            for (int e4 = 0; e4 < 16; ++e4) {
                const ulonglong2 wA0 = *(const ulonglong2*)(wr0 + (2 * e4) * 256 + j * 4);
                const ulonglong2 wB0 = *(const ulonglong2*)(wr1 + (2 * e4) * 256 + j * 4);
                const ulonglong2 wA1 = *(const ulonglong2*)(wr0 + (2 * e4 + 1) * 256 + j * 4);
                const ulonglong2 wB1 = *(const ulonglong2*)(wr1 + (2 * e4 + 1) * 256 + j * 4);
#pragma unroll
                for (int p = 0; p < 4; ++p) {
                    ulonglong2 h4 = *(const ulonglong2*)(hs + (r0 + p) * XSTRIDE + e4 * 4);
                    fma2(a0[p], h4.x, wA0.x);
                    fma2(a1[p], h4.x, wA0.y);
                    fma2(a2[p], h4.x, wB0.x);
                    fma2(a3[p], h4.x, wB0.y);
                    fma2(a0[p], h4.y, wA1.x);
                    fma2(a1[p], h4.y, wA1.y);
                    fma2(a2[p], h4.y, wB1.x);
                    fma2(a3[p], h4.y, wB1.y);
                }
            }
        }

        // epilogue
#pragma unroll
        for (int p = 0; p < 4; ++p) {
            float zi = hsum2(a0[p]);
            float zf = hsum2(a1[p]);
            float zg = hsum2(a2[p]);
            float zo = hsum2(a3[p]);
            float ig  = fsig(zi);
            float fg  = fsig(zf);
            float gg2 = ftanh(zg);
            float og  = fsig(zo);
            float c = fg * c_[p] + ig * gg2;
            c_[p] = c;
            float hv = og * ftanh(c);
            h_[p] = hv;
            out[((size_t)(nbase + r0 + p) * LL + te) * 128 + dir * 64 + j] = hv;
        }
        buf ^= 1;
    }
}

extern "C" void kernel_launch(void* const* d_in, const int* in_sizes, int n_in,
                              void* d_out, int out_size) {
    const int*   ids   = (const int*)  d_in[0];
    const float* embed = (const float*)d_in[1];
    const float* Wk_f  = (const float*)d_in[2];
    const float* Wr_f  = (const float*)d_in[3];
    const float* b_f   = (const float*)d_in[4];
    const float* Wk_b  = (const float*)d_in[5];
    const float* Wr_b  = (const float*)d_in[6];
    const float* b_b   = (const float*)d_in[7];
    float* out = (float*)d_out;

    static bool attr_set = false;
    if (!attr_set) {
        cudaFuncSetAttribute(pre_kernel,
                             cudaFuncAttributeMaxDynamicSharedMemorySize,
                             K1_SMEM_FLOATS * (int)sizeof(float));
        cudaFuncSetAttribute(rec_kernel,
                             cudaFuncAttributeMaxDynamicSharedMemorySize,
                             K2_SMEM_FLOATS * (int)sizeof(float));
        attr_set = true;
    }

    dim3 grid1((NSEQ * LL) / (K1_ROWS * K1_SUBS), 2);   // 2048 x 2
    pre_kernel<<<grid1, NTHR, K1_SMEM_FLOATS * sizeof(float)>>>(
        ids, embed, Wk_f, b_f, Wk_b, b_b);

    dim3 grid2(NSEQ / ROWS, 2);                         // 64 x 2
    rec_kernel<<<grid2, NTHR, K2_SMEM_FLOATS * sizeof(float)>>>(
        Wr_f, Wr_b, out);
}

// round 6
// speedup vs baseline: 1.1226x; 1.1226x over previous
#include <cuda_runtime.h>
#include <cstdint>

#define LL    256   // sequence length
#define EE    64    // embed dim
#define HH    64    // hidden
#define GG    256   // 4H
#define NSEQ  2048  // B*S

typedef unsigned long long u64;

// 1 GB scratch: pre[dir][n][t][j*4+g]  (input projection + bias, both directions)
__device__ float g_pre[(size_t)2 * NSEQ * LL * GG];

__device__ __forceinline__ void fma2(u64 &d, u64 a, u64 b) {
    asm("fma.rn.f32x2 %0, %1, %2, %0;" : "+l"(d) : "l"(a), "l"(b));
}
__device__ __forceinline__ u64 pack2(float lo, float hi) {
    u64 r; asm("mov.b64 %0, {%1, %2};" : "=l"(r) : "f"(lo), "f"(hi)); return r;
}
__device__ __forceinline__ float hsum2(u64 v) {
    float lo, hi; asm("mov.b64 {%0, %1}, %2;" : "=f"(lo), "=f"(hi) : "l"(v));
    return lo + hi;
}
__device__ __forceinline__ float fsig(float x) {
    return __fdividef(1.f, 1.f + __expf(-x));
}
__device__ __forceinline__ float ftanh(float x) {
    return 2.f * __fdividef(1.f, 1.f + __expf(-2.f * x)) - 1.f;
}
__device__ __forceinline__ void stcs4(float* p, float4 v) {
    asm volatile("st.global.cs.v4.f32 [%0], {%1,%2,%3,%4};"
                 :: "l"(p), "f"(v.x), "f"(v.y), "f"(v.z), "f"(v.w) : "memory");
}
__device__ __forceinline__ float4 ldcs4(const float* p) {
    float4 v;
    asm volatile("ld.global.cs.v4.f32 {%0,%1,%2,%3}, [%4];"
                 : "=f"(v.x), "=f"(v.y), "=f"(v.z), "=f"(v.w) : "l"(p));
    return v;
}

#define XSTRIDE 68

// ============================================================================
// Kernel 1: pre[dir][m][g] = embed[ids[m]] @ Wk_dir + b_dir   (m = n*LL + t)
// 256 threads, 2 CTAs/SM, 32-row subtiles (8 rows/thread), double-buffered xs.
// Weight layout in SMEM (K-paired for f32x2):
//   wk0[e2*256 + j*4 + g*2 + s] = Wk[(2*e2+s)*GG + g*64 + j]      g in {i,f}
//   wk1[e2*256 + j*4 + g*2 + s] = Wk[(2*e2+s)*GG + (g+2)*64 + j]  g in {g,o}
// ============================================================================
#define K1_NTHR 256
#define K1_ROWS 32
#define K1_SUBS 4
#define K1_SMEM_FLOATS (16384 + 2 * (K1_ROWS * XSTRIDE))

__global__ void __launch_bounds__(K1_NTHR, 2)
pre_kernel(const int* __restrict__ ids,
           const float* __restrict__ embed,
           const float* __restrict__ Wk_f, const float* __restrict__ b_f,
           const float* __restrict__ Wk_b, const float* __restrict__ b_b)
{
    extern __shared__ float smem[];
    float* wk0   = smem;
    float* wk1   = smem + 8192;
    float* xsbuf = smem + 16384;        // 2 x [32][68]

    const int tid = threadIdx.x;
    const int dir = blockIdx.y;
    const float* Wk = dir ? Wk_b : Wk_f;
    const float* bb = dir ? b_b  : b_f;

    for (int idx = tid; idx < 8192; idx += K1_NTHR) {
        int e2  = idx >> 8;
        int rem = idx & 255;
        int jj  = rem >> 2;
        int g   = (rem >> 1) & 1;
        int s   = rem & 1;
        int e   = 2 * e2 + s;
        wk0[idx] = Wk[e * GG + g * 64 + jj];
        wk1[idx] = Wk[e * GG + (g + 2) * 64 + jj];
    }

    const int j  = tid & 63;
    const int q  = tid >> 6;            // 0..3
    const int r0 = q * 8;
    const float bi = bb[j], bf = bb[64 + j], bg = bb[128 + j], bo = bb[192 + j];

    const int gr = tid >> 3;            // row 0..31
    const int ge = (tid & 7) * 8;       // e offset

    const size_t m_base = (size_t)blockIdx.x * (K1_ROWS * K1_SUBS);
    const size_t dbase  = (size_t)dir * NSEQ * LL;

    // gather subtile 0 into buffer 0
    {
        int id = ids[m_base + gr];
        const float4* src = (const float4*)(embed + (size_t)id * EE + ge);
        float4 v0 = src[0];
        float4 v1 = src[1];
        float4* dst = (float4*)&xsbuf[gr * XSTRIDE + ge];
        dst[0] = v0;
        dst[1] = v1;
    }

    int buf = 0;
    for (int sub = 0; sub < K1_SUBS; ++sub) {
        __syncthreads();   // xs[buf] ready (and weights on sub=0); xs[buf^1] free
        float* xs = xsbuf + buf * (K1_ROWS * XSTRIDE);

        // prefetch next subtile's embed rows into registers (lands under compute)
        float4 n0, n1;
        if (sub + 1 < K1_SUBS) {
            int id = ids[m_base + (size_t)(sub + 1) * K1_ROWS + gr];
            const float4* src = (const float4*)(embed + (size_t)id * EE + ge);
            n0 = src[0];
            n1 = src[1];
        }

        u64 a0[8], a1[8], a2[8], a3[8];
#pragma unroll
        for (int p = 0; p < 8; ++p) {
            a0[p] = pack2(bi, 0.f);
            a1[p] = pack2(bf, 0.f);
            a2[p] = pack2(bg, 0.f);
            a3[p] = pack2(bo, 0.f);
        }

#pragma unroll 2
        for (int e4 = 0; e4 < 16; ++e4) {
            const ulonglong2 wA0 = *(const ulonglong2*)(wk0 + (2 * e4) * 256 + j * 4);
            const ulonglong2 wB0 = *(const ulonglong2*)(wk1 + (2 * e4) * 256 + j * 4);
            const ulonglong2 wA1 = *(const ulonglong2*)(wk0 + (2 * e4 + 1) * 256 + j * 4);
            const ulonglong2 wB1 = *(const ulonglong2*)(wk1 + (2 * e4 + 1) * 256 + j * 4);
#pragma unroll
            for (int p = 0; p < 8; ++p) {
                ulonglong2 x4 = *(const ulonglong2*)(xs + (r0 + p) * XSTRIDE + e4 * 4);
                fma2(a0[p], x4.x, wA0.x);
                fma2(a1[p], x4.x, wA0.y);
                fma2(a2[p], x4.x, wB0.x);
                fma2(a3[p], x4.x, wB0.y);
                fma2(a0[p], x4.y, wA1.x);
                fma2(a1[p], x4.y, wA1.y);
                fma2(a2[p], x4.y, wB1.x);
                fma2(a3[p], x4.y, wB1.y);
            }
        }

        const size_t m0 = m_base + (size_t)sub * K1_ROWS;
#pragma unroll
        for (int p = 0; p < 8; ++p) {
            float4 r;
            r.x = hsum2(a0[p]);
            r.y = hsum2(a1[p]);
            r.z = hsum2(a2[p]);
            r.w = hsum2(a3[p]);
            stcs4(&g_pre[(dbase + m0 + r0 + p) * GG + j * 4], r);
        }

        // stage next subtile into the other buffer
        if (sub + 1 < K1_SUBS) {
            float* xn = xsbuf + (buf ^ 1) * (K1_ROWS * XSTRIDE);
            float4* dst = (float4*)&xn[gr * XSTRIDE + ge];
            dst[0] = n0;
            dst[1] = n1;
        }
        buf ^= 1;
    }
}

// ============================================================================
// Kernel 2: recurrence only (h @ Wr per step). 512 threads, 4 rows/thread.
// The h exchange is private to each 64-thread group (warps 2q, 2q+1): use a
// NAMED barrier per group so the 8 groups drift and overlap pipes.
// ============================================================================
#define K2_NTHR 512
#define ROWS 32
#define K2_SMEM_FLOATS (16384 + 2 * (ROWS * XSTRIDE))

__global__ void __launch_bounds__(K2_NTHR, 1)
rec_kernel(const float* __restrict__ Wr_f,
           const float* __restrict__ Wr_b,
           float* __restrict__ out)
{
    extern __shared__ float smem[];
    float* wr0   = smem;
    float* wr1   = smem + 8192;
    float* hsbuf = smem + 16384;       // 2 x [32][68]

    const int tid   = threadIdx.x;
    const int dir   = blockIdx.y;
    const int nbase = blockIdx.x * ROWS;
    const float* Wr = dir ? Wr_b : Wr_f;

    for (int idx = tid; idx < 8192; idx += K2_NTHR) {
        int e2  = idx >> 8;
        int rem = idx & 255;
        int jj  = rem >> 2;
        int g   = (rem >> 1) & 1;
        int s   = rem & 1;
        int e   = 2 * e2 + s;
        wr0[idx] = Wr[e * GG + g * 64 + jj];
        wr1[idx] = Wr[e * GG + (g + 2) * 64 + jj];
    }

    const int j  = tid & 63;
    const int q  = tid >> 6;           // 0..7 -> group id
    const int r0 = q * 4;              // 4 rows per thread, private to group
    const int barid = q + 1;           // named barrier per 2-warp group

    const float* preb = g_pre + (size_t)dir * NSEQ * LL * GG;

    float c_[4], h_[4];
    float4 pv[4];
#pragma unroll
    for (int p = 0; p < 4; ++p) { c_[p] = 0.f; h_[p] = 0.f; }

    // prefetch pre for step 0
    {
        const int te0 = dir ? (LL - 1) : 0;
#pragma unroll
        for (int p = 0; p < 4; ++p)
            pv[p] = ldcs4(&preb[((size_t)(nbase + r0 + p) * LL + te0) * GG + j * 4]);
    }

    __syncthreads();   // weights ready (only CTA-wide barrier)

    int buf = 0;
    for (int t = 0; t < LL; ++t) {
        const int te = dir ? (LL - 1 - t) : t;
        float* hs = hsbuf + buf * (ROWS * XSTRIDE);

        // publish h_t (rows r0..r0+3 — read only by this 64-thread group)
#pragma unroll
        for (int p = 0; p < 4; ++p)
            hs[(r0 + p) * XSTRIDE + j] = h_[p];
        asm volatile("bar.sync %0, %1;" :: "r"(barid), "r"(64) : "memory");

        // consume prefetched pre into accumulators
        u64 a0[4], a1[4], a2[4], a3[4];
#pragma unroll
        for (int p = 0; p < 4; ++p) {
            a0[p] = pack2(pv[p].x, 0.f);
            a1[p] = pack2(pv[p].y, 0.f);
            a2[p] = pack2(pv[p].z, 0.f);
            a3[p] = pack2(pv[p].w, 0.f);
        }

        // issue prefetch for step t+1 (lands during the compute below)
        {
            const int tn = (t + 1 < LL) ? (dir ? (LL - 2 - t) : (t + 1)) : te;
#pragma unroll
            for (int p = 0; p < 4; ++p)
                pv[p] = ldcs4(&preb[((size_t)(nbase + r0 + p) * LL + tn) * GG + j * 4]);
        }

        if (t != 0) {   // h == 0 at t==0: skip the matmul
#pragma unroll 4
            for (int e4 = 0; e4 < 16; ++e4) {
                const ulonglong2 wA0 = *(const ulonglong2*)(wr0 + (2 * e4) * 256 + j * 4);
                const ulonglong2 wB0 = *(const ulonglong2*)(wr1 + (2 * e4) * 256 + j * 4);
                const ulonglong2 wA1 = *(const ulonglong2*)(wr0 + (2 * e4 + 1) * 256 + j * 4);
                const ulonglong2 wB1 = *(const ulonglong2*)(wr1 + (2 * e4 + 1) * 256 + j * 4);
#pragma unroll
                for (int p = 0; p < 4; ++p) {
                    ulonglong2 h4 = *(const ulonglong2*)(hs + (r0 + p) * XSTRIDE + e4 * 4);
                    fma2(a0[p], h4.x, wA0.x);
                    fma2(a1[p], h4.x, wA0.y);
                    fma2(a2[p], h4.x, wB0.x);
                    fma2(a3[p], h4.x, wB0.y);
                    fma2(a0[p], h4.y, wA1.x);
                    fma2(a1[p], h4.y, wA1.y);
                    fma2(a2[p], h4.y, wB1.x);
                    fma2(a3[p], h4.y, wB1.y);
                }
            }
        }

        // epilogue
#pragma unroll
        for (int p = 0; p < 4; ++p) {
            float zi = hsum2(a0[p]);
            float zf = hsum2(a1[p]);
            float zg = hsum2(a2[p]);
            float zo = hsum2(a3[p]);
            float ig  = fsig(zi);
            float fg  = fsig(zf);
            float gg2 = ftanh(zg);
            float og  = fsig(zo);
            float c = fg * c_[p] + ig * gg2;
            c_[p] = c;
            float hv = og * ftanh(c);
            h_[p] = hv;
            float* op = &out[((size_t)(nbase + r0 + p) * LL + te) * 128 + dir * 64 + j];
            asm volatile("st.global.cs.f32 [%0], %1;" :: "l"(op), "f"(hv) : "memory");
        }
        buf ^= 1;
    }
}

extern "C" void kernel_launch(void* const* d_in, const int* in_sizes, int n_in,
                              void* d_out, int out_size) {
    const int*   ids   = (const int*)  d_in[0];
    const float* embed = (const float*)d_in[1];
    const float* Wk_f  = (const float*)d_in[2];
    const float* Wr_f  = (const float*)d_in[3];
    const float* b_f   = (const float*)d_in[4];
    const float* Wk_b  = (const float*)d_in[5];
    const float* Wr_b  = (const float*)d_in[6];
    const float* b_b   = (const float*)d_in[7];
    float* out = (float*)d_out;

    static bool attr_set = false;
    if (!attr_set) {
        cudaFuncSetAttribute(pre_kernel,
                             cudaFuncAttributeMaxDynamicSharedMemorySize,
                             K1_SMEM_FLOATS * (int)sizeof(float));
        cudaFuncSetAttribute(rec_kernel,
                             cudaFuncAttributeMaxDynamicSharedMemorySize,
                             K2_SMEM_FLOATS * (int)sizeof(float));
        attr_set = true;
    }

    dim3 grid1((NSEQ * LL) / (K1_ROWS * K1_SUBS), 2);   // 4096 x 2
    pre_kernel<<<grid1, K1_NTHR, K1_SMEM_FLOATS * sizeof(float)>>>(
        ids, embed, Wk_f, b_f, Wk_b, b_b);

    dim3 grid2(NSEQ / ROWS, 2);                         // 64 x 2
    rec_kernel<<<grid2, K2_NTHR, K2_SMEM_FLOATS * sizeof(float)>>>(
        Wr_f, Wr_b, out);
}